// round 16
// baseline (speedup 1.0000x reference)
#include <cuda_runtime.h>

#define NFSZ 1001
#define HSZ   256
#define BSZ   64
#define FD    128
#define INCH  16
#define G4    1024   // 4*H
#define INS0  144    // FD + INCH

// device-global scratch (allocation-free rule)
__device__ float g_Gf[NFSZ * G4];                // pre-scaled f-side gate pre-acts
__device__ unsigned long long g_mb[BSZ * 1024];  // layer0->layer1 mailboxes {tag,val}

__device__ __forceinline__ float ex2f(float x) {
    float y; asm("ex2.approx.f32 %0, %1;" : "=f"(y) : "f"(x)); return y;
}
__device__ __forceinline__ float rcpf(float x) {
    float y; asm("rcp.approx.f32 %0, %1;" : "=f"(y) : "f"(x)); return y;
}
__device__ __forceinline__ float negabsf(float x) {
    return __int_as_float(__float_as_int(x) | 0x80000000);
}
__device__ __forceinline__ unsigned long long ldv64(const unsigned long long* p) {
    unsigned long long v;
    asm volatile("ld.volatile.global.b64 %0, [%1];" : "=l"(v) : "l"(p));
    return v;
}
__device__ __forceinline__ void stv64(unsigned long long* p, unsigned long long v) {
    asm volatile("st.volatile.global.b64 [%0], %1;" :: "l"(p), "l"(v) : "memory");
}
__device__ __forceinline__ unsigned long long packtv(unsigned tag, float val) {
    return ((unsigned long long)tag << 32) | (unsigned)__float_as_int(val);
}
__device__ __forceinline__ float valof(unsigned long long v) {
    return __int_as_float((int)(unsigned)v);
}

#define L2E   1.4426950408889634f
#define NL2E2 -2.8853900817779268f

// 7-MUFU activation (R12-proven): pre-scaled gates in, returns hr, updates c.
__device__ __forceinline__ float lstm_unit(float pre_i, float pre_f, float pre_g,
                                           float pre_o, float& c) {
    float ei = ex2f(pre_i), ef = ex2f(pre_f), eo = ex2f(pre_o);
    float eg = ex2f(negabsf(pre_g));
    float pi = 1.f + ei, pf = 1.f + ef, pg = 1.f + eg;
    float PP = pi * pg;
    float R  = rcpf(PP * pf);
    float tnum = fmaf(eg, -pf, pf);                 // (1-eg)*pf
    float num  = fmaf(c, PP, copysignf(tnum, -pre_g));
    c = num * R;
    float ec = ex2f(NL2E2 * fabsf(c));
    float hm = fmaf(ec, -1.f, 1.f) * rcpf((1.f + eo) * (1.f + ec));
    return copysignf(hm, c);
}

__device__ __forceinline__ float bfly5(float v) {
    v += __shfl_xor_sync(0xffffffffu, v, 16);
    v += __shfl_xor_sync(0xffffffffu, v, 8);
    v += __shfl_xor_sync(0xffffffffu, v, 4);
    v += __shfl_xor_sync(0xffffffffu, v, 2);
    v += __shfl_xor_sync(0xffffffffu, v, 1);
    return v;
}

// ---------------- precompute: Gf = scale * (f @ Wf^T)  (layout [t][gate*256+u]) ----------------
__global__ __launch_bounds__(256) void gf_kernel(const float* __restrict__ f,
                                                 const float* __restrict__ Wih0) {
    __shared__ float Wc[256][33];
    __shared__ float fs[8][32];
    const int tid = threadIdx.x;
    const int t0  = blockIdx.x * 8;
    const int gb  = blockIdx.y * 256;

    float acc[8] = {0.f,0.f,0.f,0.f,0.f,0.f,0.f,0.f};
    for (int kc = 0; kc < FD; kc += 32) {
        #pragma unroll
        for (int i = 0; i < 32; i++) {
            int e  = i * 256 + tid;
            int gl = e >> 5, kk = e & 31;
            Wc[gl][kk] = Wih0[(gb + gl) * INS0 + kc + kk];
        }
        {
            int tt = tid >> 5, kk = tid & 31;
            int t = t0 + tt;
            fs[tt][kk] = (t < NFSZ) ? f[t * FD + kc + kk] : 0.f;
        }
        __syncthreads();
        #pragma unroll 8
        for (int kk = 0; kk < 32; kk++) {
            float w = Wc[tid][kk];
            #pragma unroll
            for (int tt = 0; tt < 8; tt++) acc[tt] = fmaf(fs[tt][kk], w, acc[tt]);
        }
        __syncthreads();
    }
    float scale = (blockIdx.y == 2) ? NL2E2 : -L2E;
    #pragma unroll
    for (int tt = 0; tt < 8; tt++) {
        int t = t0 + tt;
        if (t < NFSZ) g_Gf[t * G4 + gb + tid] = acc[tt] * scale;
    }
}

// ---------------- main LSTM: 2 CTAs per 2 batches (R12 skeleton + batch ILP) ----------------
// blk even -> role A (layer0, batches 2p and 2p+1; 256 thr, 1 unit/thread/batch)
// blk odd  -> role B (layers 1+2, two 128-thr warpgroups, 2 units/thread/batch)
// A->B: tagged gmem mailboxes (one per batch, 3-tick skew, prefetched).
// B-internal layer1->layer2: smem parity scalars. Two independent recurrence
// chains per thread fill latency bubbles (tick is dependency-latency bound).

__global__ __launch_bounds__(256, 1) void lstm_kernel(
    const float* __restrict__ x,
    const float* __restrict__ Wih0, const float* __restrict__ Whh0,
    const float* __restrict__ bih0, const float* __restrict__ bhh0,
    const float* __restrict__ Whr0,
    const float* __restrict__ Wih1, const float* __restrict__ Whh1,
    const float* __restrict__ bih1, const float* __restrict__ bhh1,
    const float* __restrict__ Whr1,
    const float* __restrict__ Wih2, const float* __restrict__ Whh2,
    const float* __restrict__ bih2, const float* __restrict__ bhh2,
    const float* __restrict__ Whr2,
    float* __restrict__ out)
{
    __shared__ __align__(16) float partA[2][2][8];     // [parity][batch][warp]
    __shared__ __align__(16) float partB[2][2][2][4];  // [parity][layer][batch][warp]
    __shared__ float fwdB[2][2];                       // [parity][batch]

    const int pr   = blockIdx.x >> 1;       // batch-pair index 0..31
    const int role = blockIdx.x & 1;
    const int tid  = threadIdx.x;
    const int b0   = pr * 2;

    if (role == 0) {
        // ============ ROLE A : layer 0, batches b0,b0+1, 1 unit/thread ============
        const int u    = tid;
        const int warp = tid >> 5;
        const int lane = tid & 31;

        float whh_s[4], base_s[2][4];
        #pragma unroll
        for (int g = 0; g < 4; g++) {
            int idx  = g * HSZ + u;
            float sc = (g == 2) ? NL2E2 : -L2E;
            whh_s[g] = Whh0[idx] * sc;
            float bias = bih0[idx] + bhh0[idx];
            #pragma unroll
            for (int bb = 0; bb < 2; bb++) {
                float acc = bias;
                #pragma unroll
                for (int kk = 0; kk < INCH; kk++)
                    acc = fmaf(x[(b0 + bb) * INCH + kk],
                               Wih0[idx * INS0 + FD + kk], acc);
                base_s[bb][g] = acc * sc;
            }
        }
        const float whr = Whr0[u];
        float c0 = 0.f, c1 = 0.f;

        if (tid < 32) ((float*)partA)[tid] = 0.f;
        __syncthreads();

        // Gf raw double buffer (shared between batches; base added at use)
        float gA[4], gB[4];
        #pragma unroll
        for (int g = 0; g < 4; g++) gA[g] = g_Gf[g * HSZ + u];
        float* gfc = gA;
        float* gfn = gB;

        unsigned long long* mb0 = &g_mb[(b0)     * 1024];
        unsigned long long* mb1 = &g_mb[(b0 + 1) * 1024];

        for (int k = 0; k <= NFSZ; k++) {
            const int par = k & 1, rp = par ^ 1;
            if (k + 1 <= NFSZ - 1) {
                const float* gp = &g_Gf[(k + 1) * G4 + u];
                #pragma unroll
                for (int g = 0; g < 4; g++) gfn[g] = gp[g * HSZ];
            }
            // h_prev per batch: sum 8 warp partials
            float4 q0 = *(const float4*)&partA[rp][0][0];
            float4 q1 = *(const float4*)&partA[rp][0][4];
            float h0 = ((q0.x + q0.y) + (q0.z + q0.w))
                     + ((q1.x + q1.y) + (q1.z + q1.w));
            float4 r0 = *(const float4*)&partA[rp][1][0];
            float4 r1 = *(const float4*)&partA[rp][1][4];
            float h1 = ((r0.x + r0.y) + (r0.z + r0.w))
                     + ((r1.x + r1.y) + (r1.z + r1.w));
            if (k >= 1 && tid == 0) {
                stv64(&mb0[k - 1], packtv((unsigned)k, h0));
                stv64(&mb1[k - 1], packtv((unsigned)k, h1));
            }
            if (k <= NFSZ - 1) {
                float p00 = fmaf(whh_s[0], h0, gfc[0] + base_s[0][0]);
                float p01 = fmaf(whh_s[1], h0, gfc[1] + base_s[0][1]);
                float p02 = fmaf(whh_s[2], h0, gfc[2] + base_s[0][2]);
                float p03 = fmaf(whh_s[3], h0, gfc[3] + base_s[0][3]);
                float p10 = fmaf(whh_s[0], h1, gfc[0] + base_s[1][0]);
                float p11 = fmaf(whh_s[1], h1, gfc[1] + base_s[1][1]);
                float p12 = fmaf(whh_s[2], h1, gfc[2] + base_s[1][2]);
                float p13 = fmaf(whh_s[3], h1, gfc[3] + base_s[1][3]);
                float hr0 = lstm_unit(p00, p01, p02, p03, c0);
                float hr1 = lstm_unit(p10, p11, p12, p13, c1);
                float s0 = bfly5(hr0 * whr);
                float s1 = bfly5(hr1 * whr);
                if (lane == 0) {
                    partA[par][0][warp] = s0;
                    partA[par][1][warp] = s1;
                }
            }
            float* tmp = gfc; gfc = gfn; gfn = tmp;
            __syncthreads();
        }
    } else {
        // ====== ROLE B : layers 1 (wg0, t=k-3) + 2 (wg1, t=k-5), 2 batches ======
        const int wg   = tid >> 7;          // 0 -> layer1, 1 -> layer2
        const int wtid = tid & 127;
        const int warp = wtid >> 5;
        const int lane = wtid & 31;
        const int u0   = wtid * 2;

        const float* Whh = wg ? Whh2 : Whh1;
        const float* Wih = wg ? Wih2 : Wih1;
        const float* bih = wg ? bih2 : bih1;
        const float* bhh = wg ? bhh2 : bhh1;
        const float* Whr = wg ? Whr2 : Whr1;
        const int skew = wg ? 5 : 3;

        float whh_s[8], base_s[8], wih_s[8];
        #pragma unroll
        for (int j = 0; j < 8; j++) {
            int gate = j >> 1;
            int idx  = gate * HSZ + u0 + (j & 1);
            float sc = (gate == 2) ? NL2E2 : -L2E;
            whh_s[j]  = Whh[idx] * sc;
            base_s[j] = (bih[idx] + bhh[idx]) * sc;
            wih_s[j]  = Wih[idx] * sc;
        }
        const float w0 = Whr[u0], w1 = Whr[u0 + 1];
        float cs[2][2] = {{0.f, 0.f}, {0.f, 0.f}};   // [batch][unit]

        if (tid < 32) ((float*)partB)[tid] = 0.f;
        if (tid < 4)  ((float*)fwdB)[tid] = 0.f;
        __syncthreads();

        unsigned long long* mbin0 = &g_mb[(b0)     * 1024];
        unsigned long long* mbin1 = &g_mb[(b0 + 1) * 1024];
        unsigned long long mv0 = 0, mv1 = 0;
        float* outp0 = out + (b0)     * NFSZ;
        float* outp1 = out + (b0 + 1) * NFSZ;

        for (int k = 0; k <= NFSZ + 5; k++) {
            const int par = k & 1, rp = par ^ 1;
            const int t = k - skew;
            const bool active = (t >= 0) && (t < NFSZ);

            float4 pa = *(const float4*)partB[rp][wg][0];
            float h0 = (pa.x + pa.y) + (pa.z + pa.w);
            float4 pb = *(const float4*)partB[rp][wg][1];
            float h1 = (pb.x + pb.y) + (pb.z + pb.w);

            float u_in0 = 0.f, u_in1 = 0.f;
            if (wg == 0) {
                if (active) {
                    const unsigned expf = (unsigned)(t + 1);
                    while ((unsigned)(mv0 >> 32) != expf) mv0 = ldv64(&mbin0[t]);
                    while ((unsigned)(mv1 >> 32) != expf) mv1 = ldv64(&mbin1[t]);
                    u_in0 = valof(mv0);
                    u_in1 = valof(mv1);
                }
                if (wtid == 0) { fwdB[par][0] = h0; fwdB[par][1] = h1; }
            } else {
                u_in0 = fwdB[rp][0];
                u_in1 = fwdB[rp][1];
                if (wtid == 0 && k >= 6) {
                    outp0[k - 6] = h0;
                    outp1[k - 6] = h1;
                }
            }

            if (active) {
                float pre0[8], pre1[8];
                #pragma unroll
                for (int j = 0; j < 8; j++) {
                    pre0[j] = fmaf(whh_s[j], h0, fmaf(wih_s[j], u_in0, base_s[j]));
                    pre1[j] = fmaf(whh_s[j], h1, fmaf(wih_s[j], u_in1, base_s[j]));
                }
                float hr00 = lstm_unit(pre0[0], pre0[2], pre0[4], pre0[6], cs[0][0]);
                float hr01 = lstm_unit(pre0[1], pre0[3], pre0[5], pre0[7], cs[0][1]);
                float hr10 = lstm_unit(pre1[0], pre1[2], pre1[4], pre1[6], cs[1][0]);
                float hr11 = lstm_unit(pre1[1], pre1[3], pre1[5], pre1[7], cs[1][1]);
                float s0 = bfly5(fmaf(hr01, w1, hr00 * w0));
                float s1 = bfly5(fmaf(hr11, w1, hr10 * w0));
                if (lane == 0) {
                    partB[par][wg][0][warp] = s0;
                    partB[par][wg][1][warp] = s1;
                }
            }
            if (wg == 0) {
                int tn = t + 1;
                if (tn >= 0 && tn < NFSZ) {
                    mv0 = ldv64(&mbin0[tn]);
                    mv1 = ldv64(&mbin1[tn]);
                }
            }
            __syncthreads();
        }
    }
}

// ---------------- launch ----------------

extern "C" void kernel_launch(void* const* d_in, const int* in_sizes, int n_in,
                              void* d_out, int out_size) {
    const float* x    = (const float*)d_in[0];
    const float* f    = (const float*)d_in[1];
    const float* Wih0 = (const float*)d_in[2];
    const float* Whh0 = (const float*)d_in[3];
    const float* bih0 = (const float*)d_in[4];
    const float* bhh0 = (const float*)d_in[5];
    const float* Whr0 = (const float*)d_in[6];
    const float* Wih1 = (const float*)d_in[7];
    const float* Whh1 = (const float*)d_in[8];
    const float* bih1 = (const float*)d_in[9];
    const float* bhh1 = (const float*)d_in[10];
    const float* Whr1 = (const float*)d_in[11];
    const float* Wih2 = (const float*)d_in[12];
    const float* Whh2 = (const float*)d_in[13];
    const float* bih2 = (const float*)d_in[14];
    const float* bhh2 = (const float*)d_in[15];
    const float* Whr2 = (const float*)d_in[16];

    gf_kernel<<<dim3(126, 4), 256>>>(f, Wih0);
    lstm_kernel<<<BSZ, 256>>>(x,
                              Wih0, Whh0, bih0, bhh0, Whr0,
                              Wih1, Whh1, bih1, bhh1, Whr1,
                              Wih2, Whh2, bih2, bhh2, Whr2,
                              (float*)d_out);
}

// round 17
// speedup vs baseline: 1.6287x; 1.6287x over previous
#include <cuda_runtime.h>

#define NFSZ 1001
#define HSZ   256
#define BSZ   64
#define FD    128
#define INCH  16
#define G4    1024   // 4*H
#define INS0  144    // FD + INCH

// device-global scratch (allocation-free rule)
__device__ float g_Gf[NFSZ * G4];                // pre-scaled f-side gate pre-acts
__device__ unsigned long long g_mb[BSZ * 1024];  // layer0->layer1 mailboxes {tag,val}

__device__ __forceinline__ float ex2f(float x) {
    float y; asm("ex2.approx.f32 %0, %1;" : "=f"(y) : "f"(x)); return y;
}
__device__ __forceinline__ float rcpf(float x) {
    float y; asm("rcp.approx.f32 %0, %1;" : "=f"(y) : "f"(x)); return y;
}
__device__ __forceinline__ float negabsf(float x) {
    return __int_as_float(__float_as_int(x) | 0x80000000);
}
__device__ __forceinline__ unsigned long long ldv64(const unsigned long long* p) {
    unsigned long long v;
    asm volatile("ld.volatile.global.b64 %0, [%1];" : "=l"(v) : "l"(p));
    return v;
}
__device__ __forceinline__ void stv64(unsigned long long* p, unsigned long long v) {
    asm volatile("st.volatile.global.b64 [%0], %1;" :: "l"(p), "l"(v) : "memory");
}
__device__ __forceinline__ unsigned long long packtv(unsigned tag, float val) {
    return ((unsigned long long)tag << 32) | (unsigned)__float_as_int(val);
}
__device__ __forceinline__ float valof(unsigned long long v) {
    return __int_as_float((int)(unsigned)v);
}

#define L2E   1.4426950408889634f
#define NL2E2 -2.8853900817779268f

// 7-MUFU activation (R12-proven): pre-scaled gates in, returns hr, updates c.
__device__ __forceinline__ float lstm_unit(float pre_i, float pre_f, float pre_g,
                                           float pre_o, float& c) {
    float ei = ex2f(pre_i), ef = ex2f(pre_f), eo = ex2f(pre_o);
    float eg = ex2f(negabsf(pre_g));
    float pi = 1.f + ei, pf = 1.f + ef, pg = 1.f + eg;
    float PP = pi * pg;
    float R  = rcpf(PP * pf);
    float tnum = fmaf(eg, -pf, pf);                 // (1-eg)*pf
    float num  = fmaf(c, PP, copysignf(tnum, -pre_g));
    c = num * R;
    float ec = ex2f(NL2E2 * fabsf(c));
    float hm = fmaf(ec, -1.f, 1.f) * rcpf((1.f + eo) * (1.f + ec));
    return copysignf(hm, c);
}

__device__ __forceinline__ float bfly5(float v) {
    v += __shfl_xor_sync(0xffffffffu, v, 16);
    v += __shfl_xor_sync(0xffffffffu, v, 8);
    v += __shfl_xor_sync(0xffffffffu, v, 4);
    v += __shfl_xor_sync(0xffffffffu, v, 2);
    v += __shfl_xor_sync(0xffffffffu, v, 1);
    return v;
}

// ---------------- precompute: Gf = scale * (f @ Wf^T)  (layout [t][gate*256+u]) ----------------
__global__ __launch_bounds__(256) void gf_kernel(const float* __restrict__ f,
                                                 const float* __restrict__ Wih0) {
    __shared__ float Wc[256][33];
    __shared__ float fs[8][32];
    const int tid = threadIdx.x;
    const int t0  = blockIdx.x * 8;
    const int gb  = blockIdx.y * 256;

    float acc[8] = {0.f,0.f,0.f,0.f,0.f,0.f,0.f,0.f};
    for (int kc = 0; kc < FD; kc += 32) {
        #pragma unroll
        for (int i = 0; i < 32; i++) {
            int e  = i * 256 + tid;
            int gl = e >> 5, kk = e & 31;
            Wc[gl][kk] = Wih0[(gb + gl) * INS0 + kc + kk];
        }
        {
            int tt = tid >> 5, kk = tid & 31;
            int t = t0 + tt;
            fs[tt][kk] = (t < NFSZ) ? f[t * FD + kc + kk] : 0.f;
        }
        __syncthreads();
        #pragma unroll 8
        for (int kk = 0; kk < 32; kk++) {
            float w = Wc[tid][kk];
            #pragma unroll
            for (int tt = 0; tt < 8; tt++) acc[tt] = fmaf(fs[tt][kk], w, acc[tt]);
        }
        __syncthreads();
    }
    float scale = (blockIdx.y == 2) ? NL2E2 : -L2E;
    #pragma unroll
    for (int tt = 0; tt < 8; tt++) {
        int t = t0 + tt;
        if (t < NFSZ) g_Gf[t * G4 + gb + tid] = acc[tt] * scale;
    }
}

// ---------------- main LSTM: 2 CTAs per batch (R12 skeleton, refined) ----------------
// blk even -> role A (layer0: 128 working thr, 2 units/thread, 4-warp bar)
// blk odd  -> role B (layers 1+2 as two 128-thr warpgroups, shared __syncthreads)
// A->B: tagged gmem mailbox (3-tick skew); wg0 prefetches the NEXT tick's word
// immediately after consuming the current one (full-tick L2 cover).
// B-internal layer1->layer2: smem parity scalar. Activation: 7-MUFU form.

__global__ __launch_bounds__(256, 1) void lstm_kernel(
    const float* __restrict__ x,
    const float* __restrict__ Wih0, const float* __restrict__ Whh0,
    const float* __restrict__ bih0, const float* __restrict__ bhh0,
    const float* __restrict__ Whr0,
    const float* __restrict__ Wih1, const float* __restrict__ Whh1,
    const float* __restrict__ bih1, const float* __restrict__ bhh1,
    const float* __restrict__ Whr1,
    const float* __restrict__ Wih2, const float* __restrict__ Whh2,
    const float* __restrict__ bih2, const float* __restrict__ bhh2,
    const float* __restrict__ Whr2,
    float* __restrict__ out)
{
    __shared__ __align__(16) float partA[2][4];      // role A: [parity][warp]
    __shared__ __align__(16) float partB[2][2][16];  // role B: [parity][layer][16]
    __shared__ float fwdB[2];                        // layer1 -> layer2 scalar

    const int b    = blockIdx.x >> 1;
    const int role = blockIdx.x & 1;
    const int tid  = threadIdx.x;

    if (role == 0) {
        // ========= ROLE A : layer 0, 128 working threads, 2 units/thread =========
        if (tid < 8) ((float*)partA)[tid] = 0.f;
        __syncthreads();
        if (tid >= 128) return;   // threads 128-255 exit; bar counts active threads

        const int warp = tid >> 5;
        const int lane = tid & 31;
        const int u0   = tid * 2;

        // j = gate*2 + m  (unit m = j&1)
        float whh_s[8], base_s[8];
        #pragma unroll
        for (int j = 0; j < 8; j++) {
            int gate = j >> 1;
            int idx  = gate * HSZ + u0 + (j & 1);
            float sc = (gate == 2) ? NL2E2 : -L2E;
            whh_s[j] = Whh0[idx] * sc;
            float acc = bih0[idx] + bhh0[idx];
            #pragma unroll
            for (int kk = 0; kk < INCH; kk++)
                acc = fmaf(x[b * INCH + kk], Wih0[idx * INS0 + FD + kk], acc);
            base_s[j] = acc * sc;
        }
        const float w0 = Whr0[u0], w1 = Whr0[u0 + 1];
        float c0 = 0.f, c1 = 0.f;

        float gfc[8], gfn[8];
        #pragma unroll
        for (int g4 = 0; g4 < 4; g4++) {
            float2 v = *(const float2*)&g_Gf[g4 * HSZ + u0];
            gfc[2 * g4]     = v.x + base_s[2 * g4];
            gfc[2 * g4 + 1] = v.y + base_s[2 * g4 + 1];
            gfn[2 * g4] = 0.f; gfn[2 * g4 + 1] = 0.f;
        }

        unsigned long long* mb = &g_mb[b * 1024];

        for (int k = 0; k <= NFSZ; k++) {
            const int par = k & 1, rp = par ^ 1;
            // off-chain prefetch of next Gf row (pre-added with base)
            if (k + 1 <= NFSZ - 1) {
                const float* gp = &g_Gf[(k + 1) * G4 + u0];
                #pragma unroll
                for (int g4 = 0; g4 < 4; g4++) {
                    float2 v = *(const float2*)(gp + g4 * HSZ);
                    gfn[2 * g4]     = v.x + base_s[2 * g4];
                    gfn[2 * g4 + 1] = v.y + base_s[2 * g4 + 1];
                }
            }
            // h_prev = output(k-1): 4 warp partials
            float4 p = *(const float4*)partA[rp];
            float h_prev = (p.x + p.y) + (p.z + p.w);
            if (k >= 1 && tid == 0)
                stv64(&mb[k - 1], packtv((unsigned)k, h_prev));
            if (k <= NFSZ - 1) {
                float pre[8];
                #pragma unroll
                for (int j = 0; j < 8; j++)
                    pre[j] = fmaf(whh_s[j], h_prev, gfc[j]);
                float hr0 = lstm_unit(pre[0], pre[2], pre[4], pre[6], c0);
                float hr1 = lstm_unit(pre[1], pre[3], pre[5], pre[7], c1);
                float partial = bfly5(fmaf(hr1, w1, hr0 * w0));
                if (lane == 0) partA[par][warp] = partial;
            }
            #pragma unroll
            for (int j = 0; j < 8; j++) gfc[j] = gfn[j];
            __syncthreads();
        }
    } else {
        // ============ ROLE B : layers 1 (wg0, t=k-3) + 2 (wg1, t=k-5) ============
        const int wg   = tid >> 7;          // 0 -> layer1, 1 -> layer2
        const int wtid = tid & 127;
        const int warp = wtid >> 5;
        const int lane = wtid & 31;
        const int u0   = wtid * 2;

        const float* Whh = wg ? Whh2 : Whh1;
        const float* Wih = wg ? Wih2 : Wih1;
        const float* bih = wg ? bih2 : bih1;
        const float* bhh = wg ? bhh2 : bhh1;
        const float* Whr = wg ? Whr2 : Whr1;
        const int skew = wg ? 5 : 3;

        float whh_s[8], base_s[8], wih_s[8];
        #pragma unroll
        for (int j = 0; j < 8; j++) {
            int gate = j >> 1;
            int idx  = gate * HSZ + u0 + (j & 1);
            float sc = (gate == 2) ? NL2E2 : -L2E;
            whh_s[j]  = Whh[idx] * sc;
            base_s[j] = (bih[idx] + bhh[idx]) * sc;
            wih_s[j]  = Wih[idx] * sc;
        }
        const float w0 = Whr[u0], w1 = Whr[u0 + 1];
        float cs0 = 0.f, cs1 = 0.f;

        if (wtid < 16) { partB[0][wg][wtid] = 0.f; partB[1][wg][wtid] = 0.f; }
        if (tid < 2)   fwdB[tid] = 0.f;
        __syncthreads();

        unsigned long long* mbin = &g_mb[b * 1024];
        unsigned long long mv = 0;   // prefetched mailbox word (layer1 only)

        for (int k = 0; k <= NFSZ + 5; k++) {
            const int par = k & 1, rp = par ^ 1;
            const int t = k - skew;
            const bool active = (t >= 0) && (t < NFSZ);

            // own h_prev: sum 16 partials
            float h_prev;
            {
                const float4* p = (const float4*)partB[rp][wg];
                float4 a = p[0], q = p[1], r = p[2], d = p[3];
                h_prev = (((a.x + a.y) + (a.z + a.w)) + ((q.x + q.y) + (q.z + q.w)))
                       + (((r.x + r.y) + (r.z + r.w)) + ((d.x + d.y) + (d.z + d.w)));
            }
            // inter-layer input scalar
            float u_in = 0.f;
            if (wg == 0) {
                if (active) {
                    unsigned exp_flag = (unsigned)(t + 1);
                    while ((unsigned)(mv >> 32) != exp_flag) mv = ldv64(&mbin[t]);
                    u_in = valof(mv);
                    // prefetch next tick's word NOW -> full tick of L2 cover
                    int tn = t + 1;
                    if (tn < NFSZ) mv = ldv64(&mbin[tn]);
                }
                if (wtid == 0) fwdB[par] = h_prev;   // forward to layer2
            } else {
                u_in = fwdB[rp];
                if (wtid == 0 && k >= 6) out[b * NFSZ + (k - 6)] = h_prev;
            }

            if (active) {
                float pre[8];
                #pragma unroll
                for (int j = 0; j < 8; j++)
                    pre[j] = fmaf(whh_s[j], h_prev, fmaf(wih_s[j], u_in, base_s[j]));
                float hr0 = lstm_unit(pre[0], pre[2], pre[4], pre[6], cs0);
                float hr1 = lstm_unit(pre[1], pre[3], pre[5], pre[7], cs1);
                float partial = fmaf(hr1, w1, hr0 * w0);
                partial += __shfl_xor_sync(0xffffffffu, partial, 16);
                partial += __shfl_xor_sync(0xffffffffu, partial, 8);
                partial += __shfl_xor_sync(0xffffffffu, partial, 4);
                if (lane < 4) partB[par][wg][warp * 4 + lane] = partial;
            }
            __syncthreads();
        }
    }
}

// ---------------- launch ----------------

extern "C" void kernel_launch(void* const* d_in, const int* in_sizes, int n_in,
                              void* d_out, int out_size) {
    const float* x    = (const float*)d_in[0];
    const float* f    = (const float*)d_in[1];
    const float* Wih0 = (const float*)d_in[2];
    const float* Whh0 = (const float*)d_in[3];
    const float* bih0 = (const float*)d_in[4];
    const float* bhh0 = (const float*)d_in[5];
    const float* Whr0 = (const float*)d_in[6];
    const float* Wih1 = (const float*)d_in[7];
    const float* Whh1 = (const float*)d_in[8];
    const float* bih1 = (const float*)d_in[9];
    const float* bhh1 = (const float*)d_in[10];
    const float* Whr1 = (const float*)d_in[11];
    const float* Wih2 = (const float*)d_in[12];
    const float* Whh2 = (const float*)d_in[13];
    const float* bih2 = (const float*)d_in[14];
    const float* bhh2 = (const float*)d_in[15];
    const float* Whr2 = (const float*)d_in[16];

    gf_kernel<<<dim3(126, 4), 256>>>(f, Wih0);
    lstm_kernel<<<2 * BSZ, 256>>>(x,
                                  Wih0, Whh0, bih0, bhh0, Whr0,
                                  Wih1, Whh1, bih1, bhh1, Whr1,
                                  Wih2, Whh2, bih2, bhh2, Whr2,
                                  (float*)d_out);
}